// round 6
// baseline (speedup 1.0000x reference)
#include <cuda_runtime.h>
#include <cuda_fp16.h>
#include <cstdint>

// ---------------------------------------------------------------- problem dims
constexpr int N_IN  = 32;
constexpr int H_IN  = 56;
constexpr int W_IN  = 56;
constexpr int C_IN  = 256;
constexpr int KH    = 3;
constexpr int KW    = 3;
constexpr int OC    = 256;
constexpr int OH    = 54;
constexpr int OW    = 54;

constexpr int M_TOTAL = N_IN * OH * OW;   // 93312
constexpr int K_TOTAL = KH * KW * C_IN;   // 2304
constexpr float SPARSE_TH = 0.01f;

// ---------------------------------------------------------------- GEMM config
constexpr int BM = 128;
constexpr int BN = 256;                      // full OC per CTA
constexpr int BK = 64;                       // 64 fp16 = 128B/row (SW128)
constexpr int NUM_CHUNKS = K_TOTAL / BK;     // 36
constexpr int X_ELEMS = N_IN * H_IN * W_IN * C_IN;  // 25690112

// smem: 4 pipeline stages, each A(16KB) + B(32KB)
constexpr int A_CHUNK_BYTES = 16384;
constexpr int B_CHUNK_BYTES = 32768;
constexpr int STAGE_BYTES   = A_CHUNK_BYTES + B_CHUNK_BYTES;   // 49152
constexpr int NUM_STAGES    = 4;
constexpr int SMEM_BYTES    = NUM_STAGES * STAGE_BYTES;        // 196608

// fp16 image of x (prepass output)
__device__ __half g_xh[X_ELEMS];
// B pre-packed in mma fragment order:
// [ck][ntile 0..31][h 0..1][lane 0..31][4 words], word w=(kstep&1)*2+r
// word = half2 { B(k), B(k+1) }, k = ck*64 + kstep*16 + r*8 + t*2, n = ntile*8 + g
__device__ uint32_t g_Bpack[NUM_CHUNKS * 32 * 256];

__device__ __forceinline__ uint32_t smem_u32(const void* p) {
    uint32_t a;
    asm("{ .reg .u64 t; cvta.to.shared.u64 t, %1; cvt.u32.u64 %0, t; }" : "=r"(a) : "l"(p));
    return a;
}

__device__ __forceinline__ void mma_f16(float* c, const uint32_t* a, const uint32_t* b) {
    asm volatile(
        "mma.sync.aligned.m16n8k16.row.col.f32.f16.f16.f32 "
        "{%0,%1,%2,%3}, {%4,%5,%6,%7}, {%8,%9}, {%0,%1,%2,%3};"
        : "+f"(c[0]), "+f"(c[1]), "+f"(c[2]), "+f"(c[3])
        : "r"(a[0]), "r"(a[1]), "r"(a[2]), "r"(a[3]), "r"(b[0]), "r"(b[1]));
}

// ---------------------------------------------------------------- prep: x -> fp16
__global__ void prep_x_kernel(const float* __restrict__ x) {
    int idx = blockIdx.x * 256 + threadIdx.x;       // float4 index
    float4 v = reinterpret_cast<const float4*>(x)[idx];
    __half2 h0 = __floats2half2_rn(v.x, v.y);
    __half2 h1 = __floats2half2_rn(v.z, v.w);
    uint2 u;
    u.x = *reinterpret_cast<uint32_t*>(&h0);
    u.y = *reinterpret_cast<uint32_t*>(&h1);
    reinterpret_cast<uint2*>(g_xh)[idx] = u;
}

// ---------------------------------------------------------------- prep: weights
__global__ void prep_B_kernel(const float* __restrict__ w) {
    int blk  = blockIdx.x;           // ck*32 + ntile
    int ck   = blk >> 5;
    int nt   = blk & 31;
    int tid  = threadIdx.x;          // = h*128 + lane*4 + word
    int h    = tid >> 7;
    int lane = (tid >> 2) & 31;
    int wrd  = tid & 3;
    int kstep = h * 2 + (wrd >> 1);
    int r     = wrd & 1;
    int g = lane >> 2, t = lane & 3;
    int n = nt * 8 + g;
    int k = ck * 64 + kstep * 16 + r * 8 + t * 2;
    int p  = k >> 8;                 // tap (kh*3+kw)
    int ic = k & 255;
    float v0 = w[n * K_TOTAL + ic * (KH * KW) + p];
    float v1 = w[n * K_TOTAL + (ic + 1) * (KH * KW) + p];
    if (fabsf(v0) < SPARSE_TH) v0 = 0.0f;
    if (fabsf(v1) < SPARSE_TH) v1 = 0.0f;
    __half2 hv = __floats2half2_rn(v0, v1);
    g_Bpack[blk * 256 + tid] = *reinterpret_cast<uint32_t*>(&hv);
}

// ---------------------------------------------------------------- main kernel
__global__ __launch_bounds__(256, 1)
void conv_mma_kernel(const float* __restrict__ bias,
                     float* __restrict__ out) {
    extern __shared__ char smem[];
    const uint32_t sb = smem_u32(smem);

    const int tid    = threadIdx.x;
    const int lane   = tid & 31;
    const int wid    = tid >> 5;
    const int warp_m = wid & 1;       // 2 x 64 rows
    const int warp_n = wid >> 1;      // 4 x 64 cols
    const int g      = lane >> 2;
    const int t      = lane & 3;

    const int bm = blockIdx.x * BM;

    // ---- A cp.async assignment: 1024 16B units/chunk
    const int la_row = tid >> 3;      // 0..31 (+32*i)
    const int la_u   = tid & 7;       // 16B unit within row
    int rowbase[4];
    #pragma unroll
    for (int i = 0; i < 4; i++) {
        int m   = bm + la_row + 32 * i;
        int n   = m / (OH * OW);
        int rem = m - n * (OH * OW);
        int oh  = rem / OW;
        int ow  = rem - oh * OW;
        rowbase[i] = ((n * H_IN + oh) * W_IN + ow) * C_IN;
    }

    auto issue_copies = [&](int ck, int stage) {
        const int p   = ck >> 2;
        const int ic0 = (ck & 3) * 64;
        const int kh  = p / 3;
        const int kw  = p - kh * 3;
        const int aoff = (kh * W_IN + kw) * C_IN + ic0 + la_u * 8;
        const uint32_t aBase = sb + stage * STAGE_BYTES;
        #pragma unroll
        for (int i = 0; i < 4; i++) {
            const __half* src = g_xh + rowbase[i] + aoff;
            uint32_t off = (uint32_t)(la_row + 32 * i) * 128 + la_u * 16;
            off ^= (off >> 3) & 0x70;               // SW128
            asm volatile("cp.async.cg.shared.global [%0], [%1], 16;"
                         :: "r"(aBase + off), "l"(src) : "memory");
        }
        // B: whole OC=256 per CTA -> straight contiguous 32KB copy
        const uint32_t bBase = aBase + A_CHUNK_BYTES;
        const uint32_t* src = g_Bpack + (size_t)ck * 32 * 256;
        #pragma unroll
        for (int ii = 0; ii < 8; ii++) {
            int idx = tid + 256 * ii;               // 16B unit, 2048 total
            asm volatile("cp.async.cg.shared.global [%0], [%1], 16;"
                         :: "r"(bBase + idx * 16), "l"(src + idx * 4) : "memory");
        }
        asm volatile("cp.async.commit_group;" ::: "memory");
    };

    // ---- accumulators: 4 M-tiles x 8 N-tiles x 4 = 128 regs
    float acc[4][8][4];
    #pragma unroll
    for (int i = 0; i < 4; i++)
        #pragma unroll
        for (int j = 0; j < 8; j++)
            #pragma unroll
            for (int r = 0; r < 4; r++)
                acc[i][j][r] = 0.0f;

    // ---- prologue: stages 0..2
    issue_copies(0, 0);
    issue_copies(1, 1);
    issue_copies(2, 2);

    int cstage = 0;   // stage holding chunk ck
    int istage = 3;   // stage to fill with chunk ck+3

    for (int ck = 0; ck < NUM_CHUNKS; ck++) {
        // wait until chunk ck has landed (allow up to 2 younger groups pending)
        if (ck < NUM_CHUNKS - 2) {
            asm volatile("cp.async.wait_group 2;" ::: "memory");
        } else if (ck < NUM_CHUNKS - 1) {
            asm volatile("cp.async.wait_group 1;" ::: "memory");
        } else {
            asm volatile("cp.async.wait_group 0;" ::: "memory");
        }
        __syncthreads();   // copy-visibility + WAR vs compute(ck-3)

        if (ck + 3 < NUM_CHUNKS) issue_copies(ck + 3, istage);

        // ---- compute chunk ck
        const uint32_t aBase = sb + cstage * STAGE_BYTES;
        const uint32_t bBase = aBase + A_CHUNK_BYTES;

        #pragma unroll
        for (int s = 0; s < 4; s++) {              // 4 k-steps of 16
            uint32_t af[4][4];
            #pragma unroll
            for (int i = 0; i < 4; i++) {
                uint32_t off = (uint32_t)(warp_m * 64 + i * 16 + (lane & 15)) * 128
                             + s * 32 + (lane >> 4) * 16;
                off ^= (off >> 3) & 0x70;
                asm volatile(
                    "ldmatrix.sync.aligned.m8n8.x4.shared.b16 {%0,%1,%2,%3}, [%4];"
                    : "=r"(af[i][0]), "=r"(af[i][1]), "=r"(af[i][2]), "=r"(af[i][3])
                    : "r"(aBase + off));
            }
            #pragma unroll
            for (int j = 0; j < 8; j++) {
                const int lt = warp_n * 8 + j;     // ntile 0..31
                uint32_t bf[2];
                asm volatile("ld.shared.v2.b32 {%0,%1}, [%2];"
                             : "=r"(bf[0]), "=r"(bf[1])
                             : "r"(bBase + lt * 1024 + (s >> 1) * 512 + lane * 16 + (s & 1) * 8));
                #pragma unroll
                for (int i = 0; i < 4; i++)
                    mma_f16(acc[i][j], af[i], bf);
            }
        }

        cstage = (cstage == NUM_STAGES - 1) ? 0 : cstage + 1;
        istage = (istage == NUM_STAGES - 1) ? 0 : istage + 1;
    }

    // ---- epilogue: registers -> gmem with bias
    #pragma unroll
    for (int j = 0; j < 8; j++) {
        const int n = warp_n * 64 + j * 8 + t * 2;
        const float bvx = __ldg(bias + n);
        const float bvy = __ldg(bias + n + 1);
        #pragma unroll
        for (int i = 0; i < 4; i++) {
            const int m = bm + warp_m * 64 + i * 16 + g;
            float2 v0, v1;
            v0.x = acc[i][j][0] + bvx;
            v0.y = acc[i][j][1] + bvy;
            v1.x = acc[i][j][2] + bvx;
            v1.y = acc[i][j][3] + bvy;
            *reinterpret_cast<float2*>(out + (size_t)m * OC + n)       = v0;
            *reinterpret_cast<float2*>(out + (size_t)(m + 8) * OC + n) = v1;
        }
    }
}

// ---------------------------------------------------------------- launch
extern "C" void kernel_launch(void* const* d_in, const int* in_sizes, int n_in,
                              void* d_out, int out_size) {
    const float* x      = (const float*)d_in[0];
    const float* weight = (const float*)d_in[1];
    const float* bias   = (const float*)d_in[2];
    float*       out    = (float*)d_out;

    static bool attr_set = false;
    if (!attr_set) {
        cudaFuncSetAttribute(conv_mma_kernel,
                             cudaFuncAttributeMaxDynamicSharedMemorySize, SMEM_BYTES);
        attr_set = true;
    }

    prep_x_kernel<<<X_ELEMS / 4 / 256, 256>>>(x);        // exact: 25088 blocks
    prep_B_kernel<<<NUM_CHUNKS * 32, 256>>>(weight);

    conv_mma_kernel<<<M_TOTAL / BM, 256, SMEM_BYTES>>>(bias, out);
}

// round 7
// speedup vs baseline: 1.3928x; 1.3928x over previous
#include <cuda_runtime.h>
#include <cuda_fp16.h>
#include <cstdint>

// ---------------------------------------------------------------- problem dims
constexpr int N_IN  = 32;
constexpr int H_IN  = 56;
constexpr int W_IN  = 56;
constexpr int C_IN  = 256;
constexpr int KH    = 3;
constexpr int KW    = 3;
constexpr int OC    = 256;
constexpr int OH    = 54;
constexpr int OW    = 54;

constexpr int M_TOTAL = N_IN * OH * OW;   // 93312
constexpr int K_TOTAL = KH * KW * C_IN;   // 2304
constexpr float SPARSE_TH = 0.01f;

// ---------------------------------------------------------------- GEMM config
constexpr int BM = 128;
constexpr int BN = 128;
constexpr int BK = 64;                       // 64 fp16 = 128B/row (SW128)
constexpr int NUM_CHUNKS = K_TOTAL / BK;     // 36
constexpr int X_ELEMS = N_IN * H_IN * W_IN * C_IN;  // 25690112

// smem: A-only, 3 pipeline stages of 16KB
constexpr int A_CHUNK_BYTES = 16384;
constexpr int NUM_STAGES    = 3;
constexpr int SMEM_BYTES    = NUM_STAGES * A_CHUNK_BYTES;  // 49152

// fp16 image of x (prepass output)
__device__ __half g_xh[X_ELEMS];
// B pre-packed in mma fragment order (L2-resident, read directly by MMA loop):
// [ck][ntile 0..31][h 0..1][lane 0..31][4 words], word w=(kstep&1)*2+r
// word = half2 { B(k), B(k+1) }, k = ck*64 + kstep*16 + r*8 + t*2, n = ntile*8 + g
__device__ uint32_t g_Bpack[NUM_CHUNKS * 32 * 256];

__device__ __forceinline__ uint32_t smem_u32(const void* p) {
    uint32_t a;
    asm("{ .reg .u64 t; cvta.to.shared.u64 t, %1; cvt.u32.u64 %0, t; }" : "=r"(a) : "l"(p));
    return a;
}

__device__ __forceinline__ void mma_f16(float* c, const uint32_t* a, const uint32_t* b) {
    asm volatile(
        "mma.sync.aligned.m16n8k16.row.col.f32.f16.f16.f32 "
        "{%0,%1,%2,%3}, {%4,%5,%6,%7}, {%8,%9}, {%0,%1,%2,%3};"
        : "+f"(c[0]), "+f"(c[1]), "+f"(c[2]), "+f"(c[3])
        : "r"(a[0]), "r"(a[1]), "r"(a[2]), "r"(a[3]), "r"(b[0]), "r"(b[1]));
}

// ---------------------------------------------------------------- prep: x -> fp16
__global__ void prep_x_kernel(const float* __restrict__ x) {
    int idx = blockIdx.x * 256 + threadIdx.x;       // float4 index
    float4 v = reinterpret_cast<const float4*>(x)[idx];
    __half2 h0 = __floats2half2_rn(v.x, v.y);
    __half2 h1 = __floats2half2_rn(v.z, v.w);
    uint2 u;
    u.x = *reinterpret_cast<uint32_t*>(&h0);
    u.y = *reinterpret_cast<uint32_t*>(&h1);
    reinterpret_cast<uint2*>(g_xh)[idx] = u;
}

// ---------------------------------------------------------------- prep: weights
__global__ void prep_B_kernel(const float* __restrict__ w) {
    int blk  = blockIdx.x;           // ck*32 + ntile
    int ck   = blk >> 5;
    int nt   = blk & 31;
    int tid  = threadIdx.x;          // = h*128 + lane*4 + word
    int h    = tid >> 7;
    int lane = (tid >> 2) & 31;
    int wrd  = tid & 3;
    int kstep = h * 2 + (wrd >> 1);
    int r     = wrd & 1;
    int g = lane >> 2, t = lane & 3;
    int n = nt * 8 + g;
    int k = ck * 64 + kstep * 16 + r * 8 + t * 2;
    int p  = k >> 8;                 // tap (kh*3+kw)
    int ic = k & 255;
    float v0 = w[n * K_TOTAL + ic * (KH * KW) + p];
    float v1 = w[n * K_TOTAL + (ic + 1) * (KH * KW) + p];
    if (fabsf(v0) < SPARSE_TH) v0 = 0.0f;
    if (fabsf(v1) < SPARSE_TH) v1 = 0.0f;
    __half2 hv = __floats2half2_rn(v0, v1);
    g_Bpack[blk * 256 + tid] = *reinterpret_cast<uint32_t*>(&hv);
}

// ---------------------------------------------------------------- main kernel
__global__ __launch_bounds__(256, 2)
void conv_mma_kernel(const float* __restrict__ bias,
                     float* __restrict__ out) {
    extern __shared__ char smem[];
    const uint32_t sb = smem_u32(smem);

    const int tid    = threadIdx.x;
    const int lane   = tid & 31;
    const int wid    = tid >> 5;
    const int warp_m = wid & 1;       // 2 x 64 rows
    const int warp_n = wid >> 1;      // 4 x 32 cols
    const int g      = lane >> 2;
    const int t      = lane & 3;

    const int bm = blockIdx.y * BM;
    const int bn = blockIdx.x * BN;

    // ---- A cp.async assignment: 1024 16B units/chunk
    const int la_row = tid >> 3;      // 0..31 (+32*i)
    const int la_u   = tid & 7;       // 16B unit within row
    int rowbase[4];
    #pragma unroll
    for (int i = 0; i < 4; i++) {
        int m   = bm + la_row + 32 * i;
        int n   = m / (OH * OW);
        int rem = m - n * (OH * OW);
        int oh  = rem / OW;
        int ow  = rem - oh * OW;
        rowbase[i] = ((n * H_IN + oh) * W_IN + ow) * C_IN;
    }

    auto issue_copies = [&](int ck, int stage) {
        const int p   = ck >> 2;
        const int ic0 = (ck & 3) * 64;
        const int kh  = p / 3;
        const int kw  = p - kh * 3;
        const int aoff = (kh * W_IN + kw) * C_IN + ic0 + la_u * 8;
        const uint32_t aBase = sb + stage * A_CHUNK_BYTES;
        #pragma unroll
        for (int i = 0; i < 4; i++) {
            const __half* src = g_xh + rowbase[i] + aoff;
            uint32_t off = (uint32_t)(la_row + 32 * i) * 128 + la_u * 16;
            off ^= (off >> 3) & 0x70;               // SW128
            asm volatile("cp.async.cg.shared.global [%0], [%1], 16;"
                         :: "r"(aBase + off), "l"(src) : "memory");
        }
        asm volatile("cp.async.commit_group;" ::: "memory");
    };

    // ---- accumulators
    float acc[4][4][4];
    #pragma unroll
    for (int i = 0; i < 4; i++)
        #pragma unroll
        for (int j = 0; j < 4; j++)
            #pragma unroll
            for (int r = 0; r < 4; r++)
                acc[i][j][r] = 0.0f;

    // ---- prologue: stages 0,1
    issue_copies(0, 0);
    issue_copies(1, 1);

    int cstage = 0;
    int istage = 2;

    for (int ck = 0; ck < NUM_CHUNKS; ck++) {
        if (ck < NUM_CHUNKS - 1) {
            asm volatile("cp.async.wait_group 1;" ::: "memory");
        } else {
            asm volatile("cp.async.wait_group 0;" ::: "memory");
        }
        __syncthreads();   // copy-visibility + WAR vs compute(ck-1)

        if (ck + 2 < NUM_CHUNKS) issue_copies(ck + 2, istage);

        // ---- compute chunk ck: A from smem (ldmatrix), B direct from L2 (__ldg)
        const uint32_t aBase = sb + cstage * A_CHUNK_BYTES;
        // uint2 units: ntile block = 128 uint2
        const uint2* bbase = reinterpret_cast<const uint2*>(g_Bpack)
                           + (size_t)(ck * 32 + (bn >> 3) + warp_n * 4) * 128;

        #pragma unroll
        for (int s = 0; s < 4; s++) {              // 4 k-steps of 16
            uint32_t af[4][4];
            #pragma unroll
            for (int i = 0; i < 4; i++) {
                uint32_t off = (uint32_t)(warp_m * 64 + i * 16 + (lane & 15)) * 128
                             + s * 32 + (lane >> 4) * 16;
                off ^= (off >> 3) & 0x70;
                asm volatile(
                    "ldmatrix.sync.aligned.m8n8.x4.shared.b16 {%0,%1,%2,%3}, [%4];"
                    : "=r"(af[i][0]), "=r"(af[i][1]), "=r"(af[i][2]), "=r"(af[i][3])
                    : "r"(aBase + off));
            }
            #pragma unroll
            for (int j = 0; j < 4; j++) {
                uint2 bv = __ldg(bbase + j * 128 + (s >> 1) * 64 + lane * 2 + (s & 1));
                uint32_t bf[2] = { bv.x, bv.y };
                #pragma unroll
                for (int i = 0; i < 4; i++)
                    mma_f16(acc[i][j], af[i], bf);
            }
        }

        cstage = (cstage == NUM_STAGES - 1) ? 0 : cstage + 1;
        istage = (istage == NUM_STAGES - 1) ? 0 : istage + 1;
    }

    // ---- epilogue: registers -> gmem with bias
    #pragma unroll
    for (int j = 0; j < 4; j++) {
        const int n = bn + warp_n * 32 + j * 8 + t * 2;
        const float bvx = __ldg(bias + n);
        const float bvy = __ldg(bias + n + 1);
        #pragma unroll
        for (int i = 0; i < 4; i++) {
            const int m = bm + warp_m * 64 + i * 16 + g;
            float2 v0, v1;
            v0.x = acc[i][j][0] + bvx;
            v0.y = acc[i][j][1] + bvy;
            v1.x = acc[i][j][2] + bvx;
            v1.y = acc[i][j][3] + bvy;
            *reinterpret_cast<float2*>(out + (size_t)m * OC + n)       = v0;
            *reinterpret_cast<float2*>(out + (size_t)(m + 8) * OC + n) = v1;
        }
    }
}

// ---------------------------------------------------------------- launch
extern "C" void kernel_launch(void* const* d_in, const int* in_sizes, int n_in,
                              void* d_out, int out_size) {
    const float* x      = (const float*)d_in[0];
    const float* weight = (const float*)d_in[1];
    const float* bias   = (const float*)d_in[2];
    float*       out    = (float*)d_out;

    static bool attr_set = false;
    if (!attr_set) {
        cudaFuncSetAttribute(conv_mma_kernel,
                             cudaFuncAttributeMaxDynamicSharedMemorySize, SMEM_BYTES);
        attr_set = true;
    }

    prep_x_kernel<<<X_ELEMS / 4 / 256, 256>>>(x);        // exact: 25088 blocks
    prep_B_kernel<<<NUM_CHUNKS * 32, 256>>>(weight);

    dim3 grid(OC / BN, M_TOTAL / BM);  // (2, 729)
    conv_mma_kernel<<<grid, 256, SMEM_BYTES>>>(bias, out);
}

// round 8
// speedup vs baseline: 1.4457x; 1.0380x over previous
#include <cuda_runtime.h>
#include <cuda_fp16.h>
#include <cstdint>

// ---------------------------------------------------------------- problem dims
constexpr int N_IN  = 32;
constexpr int H_IN  = 56;
constexpr int W_IN  = 56;
constexpr int C_IN  = 256;
constexpr int KH    = 3;
constexpr int KW    = 3;
constexpr int OC    = 256;
constexpr int OH    = 54;
constexpr int OW    = 54;

constexpr int M_TOTAL = N_IN * OH * OW;   // 93312
constexpr int K_TOTAL = KH * KW * C_IN;   // 2304
constexpr float SPARSE_TH = 0.01f;

// ---------------------------------------------------------------- GEMM config
constexpr int BM = 128;
constexpr int BN = 128;
constexpr int BK = 64;                       // 64 fp16 = 128B/row (SW128)
constexpr int NUM_CHUNKS = K_TOTAL / BK;     // 36
constexpr int X_ELEMS = N_IN * H_IN * W_IN * C_IN;  // 25690112

// smem: 2 stages, each A(16KB)+B(16KB)  (R4 winner layout)
constexpr int A_CHUNK_BYTES = 16384;
constexpr int B_CHUNK_BYTES = 16384;
constexpr int STAGE_BYTES   = A_CHUNK_BYTES + B_CHUNK_BYTES;   // 32768
constexpr int SMEM_BYTES    = 2 * STAGE_BYTES;                 // 65536

// fp16 image of x
__device__ __half g_xh[X_ELEMS];
// B pre-packed in mma fragment order:
// [ck][ntile 0..31][h 0..1][lane 0..31][4 words], word w=(kstep&1)*2+r
// word = half2 { B(k), B(k+1) }, k = ck*64 + kstep*16 + r*8 + t*2, n = ntile*8 + g
__device__ uint32_t g_Bpack[NUM_CHUNKS * 32 * 256];

// merged prep grid split
constexpr int PREP_X_BLOCKS = X_ELEMS / 8 / 256;   // 12544 (32B/thread, exact)
constexpr int PREP_B_BLOCKS = NUM_CHUNKS * 32;     // 1152
constexpr int PREP_BLOCKS   = PREP_X_BLOCKS + PREP_B_BLOCKS;

__device__ __forceinline__ uint32_t smem_u32(const void* p) {
    uint32_t a;
    asm("{ .reg .u64 t; cvta.to.shared.u64 t, %1; cvt.u32.u64 %0, t; }" : "=r"(a) : "l"(p));
    return a;
}

__device__ __forceinline__ void mma_f16(float* c, const uint32_t* a, const uint32_t* b) {
    asm volatile(
        "mma.sync.aligned.m16n8k16.row.col.f32.f16.f16.f32 "
        "{%0,%1,%2,%3}, {%4,%5,%6,%7}, {%8,%9}, {%0,%1,%2,%3};"
        : "+f"(c[0]), "+f"(c[1]), "+f"(c[2]), "+f"(c[3])
        : "r"(a[0]), "r"(a[1]), "r"(a[2]), "r"(a[3]), "r"(b[0]), "r"(b[1]));
}

// ---------------------------------------------------------------- merged prep
__global__ void prep_kernel(const float* __restrict__ x, const float* __restrict__ w) {
    if (blockIdx.x < PREP_X_BLOCKS) {
        // x -> fp16, 32B per thread
        int idx = (blockIdx.x * 256 + threadIdx.x) * 2;     // float4 index, 2 per thread
        #pragma unroll
        for (int q = 0; q < 2; q++) {
            float4 v = reinterpret_cast<const float4*>(x)[idx + q];
            __half2 h0 = __floats2half2_rn(v.x, v.y);
            __half2 h1 = __floats2half2_rn(v.z, v.w);
            uint2 u;
            u.x = *reinterpret_cast<uint32_t*>(&h0);
            u.y = *reinterpret_cast<uint32_t*>(&h1);
            reinterpret_cast<uint2*>(g_xh)[idx + q] = u;
        }
    } else {
        // weights: threshold + fp16 + fragment-order pack
        int blk  = blockIdx.x - PREP_X_BLOCKS;   // ck*32 + ntile
        int ck   = blk >> 5;
        int nt   = blk & 31;
        int tid  = threadIdx.x;                  // h*128 + lane*4 + word
        int h    = tid >> 7;
        int lane = (tid >> 2) & 31;
        int wrd  = tid & 3;
        int kstep = h * 2 + (wrd >> 1);
        int r     = wrd & 1;
        int g = lane >> 2, t = lane & 3;
        int n = nt * 8 + g;
        int k = ck * 64 + kstep * 16 + r * 8 + t * 2;
        int p  = k >> 8;                         // tap (kh*3+kw)
        int ic = k & 255;
        float v0 = w[n * K_TOTAL + ic * (KH * KW) + p];
        float v1 = w[n * K_TOTAL + (ic + 1) * (KH * KW) + p];
        if (fabsf(v0) < SPARSE_TH) v0 = 0.0f;
        if (fabsf(v1) < SPARSE_TH) v1 = 0.0f;
        __half2 hv = __floats2half2_rn(v0, v1);
        g_Bpack[blk * 256 + tid] = *reinterpret_cast<uint32_t*>(&hv);
    }
}

// ---------------------------------------------------------------- main kernel
__global__ __launch_bounds__(256, 2)
void conv_mma_kernel(const float* __restrict__ bias,
                     float* __restrict__ out) {
    extern __shared__ char smem[];
    const uint32_t sb = smem_u32(smem);

    const int tid    = threadIdx.x;
    const int lane   = tid & 31;
    const int wid    = tid >> 5;
    const int warp_m = wid & 1;       // 2 x 64 rows
    const int warp_n = wid >> 1;      // 4 x 32 cols
    const int g      = lane >> 2;
    const int t      = lane & 3;

    const int bm = blockIdx.y * BM;
    const int bn = blockIdx.x * BN;

    // de-lockstep co-resident CTA pairs (bid, bid+148 -> y, y+74)
    const int phase = ((blockIdx.y / 74) & 1) * (NUM_CHUNKS / 2);

    // ---- A cp.async assignment: 1024 16B units/chunk
    const int la_row = tid >> 3;      // 0..31 (+32*i)
    const int la_u   = tid & 7;       // 16B unit within row
    int rowbase[4];
    #pragma unroll
    for (int i = 0; i < 4; i++) {
        int m   = bm + la_row + 32 * i;
        int n   = m / (OH * OW);
        int rem = m - n * (OH * OW);
        int oh  = rem / OW;
        int ow  = rem - oh * OW;
        rowbase[i] = ((n * H_IN + oh) * W_IN + ow) * C_IN;
    }

    auto issue_copies = [&](int ck, int buf) {
        const int p   = ck >> 2;
        const int ic0 = (ck & 3) * 64;
        const int kh  = p / 3;
        const int kw  = p - kh * 3;
        const int aoff = (kh * W_IN + kw) * C_IN + ic0 + la_u * 8;
        const uint32_t aBase = sb + buf * STAGE_BYTES;
        #pragma unroll
        for (int i = 0; i < 4; i++) {
            const __half* src = g_xh + rowbase[i] + aoff;
            uint32_t off = (uint32_t)(la_row + 32 * i) * 128 + la_u * 16;
            off ^= (off >> 3) & 0x70;               // SW128
            asm volatile("cp.async.cg.shared.global [%0], [%1], 16;"
                         :: "r"(aBase + off), "l"(src) : "memory");
        }
        const uint32_t bBase = aBase + A_CHUNK_BYTES;
        const uint32_t* src = g_Bpack + (size_t)(ck * 32 + (bn >> 3)) * 256;
        #pragma unroll
        for (int ii = 0; ii < 4; ii++) {
            int idx = tid + 256 * ii;
            asm volatile("cp.async.cg.shared.global [%0], [%1], 16;"
                         :: "r"(bBase + idx * 16), "l"(src + idx * 4) : "memory");
        }
        asm volatile("cp.async.commit_group;" ::: "memory");
    };

    auto ckmap = [&](int cc) {
        int ck = cc + phase;
        return (ck >= NUM_CHUNKS) ? ck - NUM_CHUNKS : ck;
    };

    // ---- accumulators
    float acc[4][4][4];
    #pragma unroll
    for (int i = 0; i < 4; i++)
        #pragma unroll
        for (int j = 0; j < 4; j++)
            #pragma unroll
            for (int r = 0; r < 4; r++)
                acc[i][j][r] = 0.0f;

    // ---- prologue: chunk cc=0 -> buf 0
    issue_copies(ckmap(0), 0);

    for (int cc = 0; cc < NUM_CHUNKS; cc++) {
        const int buf = cc & 1;

        // WAR: all warps done computing on buf before its overwrite below
        __syncthreads();

        if (cc + 1 < NUM_CHUNKS) {
            issue_copies(ckmap(cc + 1), buf ^ 1);
            asm volatile("cp.async.wait_group 1;" ::: "memory");   // chunk cc landed
        } else {
            asm volatile("cp.async.wait_group 0;" ::: "memory");
        }
        __syncthreads();

        // ---- compute chunk cc from buf
        const uint32_t aBase = sb + buf * STAGE_BYTES;
        const uint32_t bBase = aBase + A_CHUNK_BYTES;

        #pragma unroll
        for (int s = 0; s < 4; s++) {              // 4 k-steps of 16
            uint32_t af[4][4];
            #pragma unroll
            for (int i = 0; i < 4; i++) {
                uint32_t off = (uint32_t)(warp_m * 64 + i * 16 + (lane & 15)) * 128
                             + s * 32 + (lane >> 4) * 16;
                off ^= (off >> 3) & 0x70;
                asm volatile(
                    "ldmatrix.sync.aligned.m8n8.x4.shared.b16 {%0,%1,%2,%3}, [%4];"
                    : "=r"(af[i][0]), "=r"(af[i][1]), "=r"(af[i][2]), "=r"(af[i][3])
                    : "r"(aBase + off));
            }
            #pragma unroll
            for (int j = 0; j < 4; j++) {
                const int lt = warp_n * 4 + j;
                uint32_t bf[2];
                asm volatile("ld.shared.v2.b32 {%0,%1}, [%2];"
                             : "=r"(bf[0]), "=r"(bf[1])
                             : "r"(bBase + lt * 1024 + (s >> 1) * 512 + lane * 16 + (s & 1) * 8));
                #pragma unroll
                for (int i = 0; i < 4; i++)
                    mma_f16(acc[i][j], af[i], bf);
            }
        }
    }

    // ---- epilogue: registers -> gmem with bias
    #pragma unroll
    for (int j = 0; j < 4; j++) {
        const int n = bn + warp_n * 32 + j * 8 + t * 2;
        const float bvx = __ldg(bias + n);
        const float bvy = __ldg(bias + n + 1);
        #pragma unroll
        for (int i = 0; i < 4; i++) {
            const int m = bm + warp_m * 64 + i * 16 + g;
            float2 v0, v1;
            v0.x = acc[i][j][0] + bvx;
            v0.y = acc[i][j][1] + bvy;
            v1.x = acc[i][j][2] + bvx;
            v1.y = acc[i][j][3] + bvy;
            *reinterpret_cast<float2*>(out + (size_t)m * OC + n)       = v0;
            *reinterpret_cast<float2*>(out + (size_t)(m + 8) * OC + n) = v1;
        }
    }
}

// ---------------------------------------------------------------- launch
extern "C" void kernel_launch(void* const* d_in, const int* in_sizes, int n_in,
                              void* d_out, int out_size) {
    const float* x      = (const float*)d_in[0];
    const float* weight = (const float*)d_in[1];
    const float* bias   = (const float*)d_in[2];
    float*       out    = (float*)d_out;

    static bool attr_set = false;
    if (!attr_set) {
        cudaFuncSetAttribute(conv_mma_kernel,
                             cudaFuncAttributeMaxDynamicSharedMemorySize, SMEM_BYTES);
        attr_set = true;
    }

    prep_kernel<<<PREP_BLOCKS, 256>>>(x, weight);

    dim3 grid(OC / BN, M_TOTAL / BM);  // (2, 729)
    conv_mma_kernel<<<grid, 256, SMEM_BYTES>>>(bias, out);
}